// round 10
// baseline (speedup 1.0000x reference)
#include <cuda_runtime.h>
#include <math.h>

#define BB 32
#define HH 32
#define KVHH 8
#define DD 128
#define GG 4
#define BLK_SZ 16
#define MAX_BLOCKS 128
#define NSPLIT 8
#define NWARP 8
#define NTHREADS 256

// Scratch (allocation-free: __device__ globals)
__device__ float g_pacc[BB * KVHH * NSPLIT * GG * DD];  // 4 MB split partials
__device__ float g_pl[BB * KVHH * NSPLIT * GG];
__device__ float g_qrot[BB * HH * DD];    // RoPE'd q, scale folded
__device__ float g_krot[BB * KVHH * DD];  // RoPE'd new k

// ---------------- prep: RoPE q and new-k once (R7-proven) ----------------
__global__ __launch_bounds__(DD) void rope_prep_kernel(
    const float* __restrict__ query,
    const float* __restrict__ key,
    const int*   __restrict__ context_lens)
{
    const int b = blockIdx.x;
    const int h = blockIdx.y;   // 0..HH-1 q head, HH..HH+KVHH-1 k head
    const int d = threadIdx.x;

    const float pos = (float)context_lens[b];
    const int fi = d & 63;
    const float inv = exp2f(-(float)fi * 0.2076205092783674f);  // log2(10000)/64
    float s, c;
    sincosf(pos * inv, &s, &c);

    if (h < HH) {
        const float* base = query + ((long)b * HH + h) * DD;
        float x = base[d];
        float other = (d < 64) ? -base[d + 64] : base[d - 64];
        g_qrot[((long)b * HH + h) * DD + d] =
            (x * c + other * s) * 0.08838834764831845f;  // D^-0.5
    } else {
        const int kh = h - HH;
        const float* base = key + ((long)b * KVHH + kh) * DD;
        float x = base[d];
        float other = (d < 64) ? -base[d + 64] : base[d - 64];
        g_krot[((long)b * KVHH + kh) * DD + d] = x * c + other * s;
    }
}

// ------- per-token update: 16-lane head-pair groups -------
// lane = 16*hi + gl. Group hi owns heads {2hi, 2hi+1}; lane owns dims gl*8..gl*8+7.
// Reduce = 1 fold + 3 butterflies (4 SHFL), 1 exp/lane, 1 SHFL p-swap.
__device__ __forceinline__ void upd_token(
    const float4& kA, const float4& kB, const float4& vA, const float4& vB,
    const float4 qh[2][2], float& l_own, float4 acc[2][2], int odd)
{
    float sc0 = kA.x * qh[0][0].x + kA.y * qh[0][0].y + kA.z * qh[0][0].z + kA.w * qh[0][0].w
              + kB.x * qh[0][1].x + kB.y * qh[0][1].y + kB.z * qh[0][1].z + kB.w * qh[0][1].w;
    float sc1 = kA.x * qh[1][0].x + kA.y * qh[1][0].y + kA.z * qh[1][0].z + kA.w * qh[1][0].w
              + kB.x * qh[1][1].x + kB.y * qh[1][1].y + kB.z * qh[1][1].z + kB.w * qh[1][1].w;

    float keep = odd ? sc1 : sc0;
    float send = odd ? sc0 : sc1;
    float v = keep + __shfl_xor_sync(0xffffffffu, send, 1);
    v += __shfl_xor_sync(0xffffffffu, v, 2);
    v += __shfl_xor_sync(0xffffffffu, v, 4);
    v += __shfl_xor_sync(0xffffffffu, v, 8);
    // v = full score of head (2*hi + odd)

    float p = __expf(v);
    l_own += p;
    float po = __shfl_xor_sync(0xffffffffu, p, 1);
    float p0 = odd ? po : p;
    float p1 = odd ? p : po;

    acc[0][0].x += p0 * vA.x; acc[0][0].y += p0 * vA.y; acc[0][0].z += p0 * vA.z; acc[0][0].w += p0 * vA.w;
    acc[0][1].x += p0 * vB.x; acc[0][1].y += p0 * vB.y; acc[0][1].z += p0 * vB.z; acc[0][1].w += p0 * vB.w;
    acc[1][0].x += p1 * vA.x; acc[1][0].y += p1 * vA.y; acc[1][0].z += p1 * vA.z; acc[1][0].w += p1 * vA.w;
    acc[1][1].x += p1 * vB.x; acc[1][1].y += p1 * vB.y; acc[1][1].z += p1 * vB.z; acc[1][1].w += p1 * vB.w;
}

// ---------------- split flash-decode (R7 skeleton, new lane mapping) ----------------
__global__ __launch_bounds__(NTHREADS) void pa_split_kernel(
    const float* __restrict__ value,
    const float* __restrict__ k_cache,
    const float* __restrict__ v_cache,
    const int*   __restrict__ block_table,
    const int*   __restrict__ context_lens)
{
    const int split = blockIdx.x;
    const int kvh   = blockIdx.y;
    const int b     = blockIdx.z;
    const int tid   = threadIdx.x;
    const int lane  = tid & 31;
    const int w     = tid >> 5;
    const int gl    = lane & 15;   // position in 16-lane group
    const int hi    = lane >> 4;   // head-pair selector (0 or 1)
    const int odd   = lane & 1;
    const int d0    = gl * 8;      // lane's dim offset (8 dims)

    const int ctx   = context_lens[b];
    const int chunk = (ctx + NSPLIT - 1) / NSPLIT;
    const int s0    = split * chunk;
    const int s1    = min(s0 + chunk, ctx);
    const int last  = ctx - 1;
    const int end   = min(s1, last);

    __shared__ int   btab[MAX_BLOCKS];
    __shared__ float wl[NWARP][GG];
    __shared__ float wacc[NWARP][GG][DD];

    for (int i = tid; i < MAX_BLOCKS; i += NTHREADS)
        btab[i] = block_table[b * MAX_BLOCKS + i];
    __syncthreads();

    // lane's 2 heads: global head idx kvh*GG + 2*hi + j
    float4 qh[2][2];
#pragma unroll
    for (int j = 0; j < 2; j++) {
        const float* qp = &g_qrot[((long)b * HH + kvh * GG + 2 * hi + j) * DD + d0];
        qh[j][0] = *(const float4*)(qp);
        qh[j][1] = *(const float4*)(qp + 4);
    }

    float l_own = 0.f;
    float4 acc[2][2];
#pragma unroll
    for (int j = 0; j < 2; j++)
#pragma unroll
        for (int h = 0; h < 2; h++)
            acc[j][h].x = acc[j][h].y = acc[j][h].z = acc[j][h].w = 0.f;

    const unsigned hoff = (unsigned)kvh * DD + d0;

    int s = s0 + w;
    // 4x unrolled, unconditional batched loads
    while (s + 3 * NWARP < end) {
        unsigned o0, o1, o2, o3;
        {
            int t0 = s, t1 = s + NWARP, t2 = s + 2 * NWARP, t3 = s + 3 * NWARP;
            o0 = (((unsigned)btab[t0 >> 4] * BLK_SZ + (t0 & 15)) * (KVHH * DD)) + hoff;
            o1 = (((unsigned)btab[t1 >> 4] * BLK_SZ + (t1 & 15)) * (KVHH * DD)) + hoff;
            o2 = (((unsigned)btab[t2 >> 4] * BLK_SZ + (t2 & 15)) * (KVHH * DD)) + hoff;
            o3 = (((unsigned)btab[t3 >> 4] * BLK_SZ + (t3 & 15)) * (KVHH * DD)) + hoff;
        }
        float4 k0A = *(const float4*)(k_cache + o0);
        float4 k0B = *(const float4*)(k_cache + o0 + 4);
        float4 v0A = *(const float4*)(v_cache + o0);
        float4 v0B = *(const float4*)(v_cache + o0 + 4);
        float4 k1A = *(const float4*)(k_cache + o1);
        float4 k1B = *(const float4*)(k_cache + o1 + 4);
        float4 v1A = *(const float4*)(v_cache + o1);
        float4 v1B = *(const float4*)(v_cache + o1 + 4);
        float4 k2A = *(const float4*)(k_cache + o2);
        float4 k2B = *(const float4*)(k_cache + o2 + 4);
        float4 v2A = *(const float4*)(v_cache + o2);
        float4 v2B = *(const float4*)(v_cache + o2 + 4);
        float4 k3A = *(const float4*)(k_cache + o3);
        float4 k3B = *(const float4*)(k_cache + o3 + 4);
        float4 v3A = *(const float4*)(v_cache + o3);
        float4 v3B = *(const float4*)(v_cache + o3 + 4);

        upd_token(k0A, k0B, v0A, v0B, qh, l_own, acc, odd);
        upd_token(k1A, k1B, v1A, v1B, qh, l_own, acc, odd);
        upd_token(k2A, k2B, v2A, v2B, qh, l_own, acc, odd);
        upd_token(k3A, k3B, v3A, v3B, qh, l_own, acc, odd);
        s += 4 * NWARP;
    }
    while (s < end) {
        unsigned off = (((unsigned)btab[s >> 4] * BLK_SZ + (s & 15)) * (KVHH * DD)) + hoff;
        float4 kA = *(const float4*)(k_cache + off);
        float4 kB = *(const float4*)(k_cache + off + 4);
        float4 vA = *(const float4*)(v_cache + off);
        float4 vB = *(const float4*)(v_cache + off + 4);
        upd_token(kA, kB, vA, vB, qh, l_own, acc, odd);
        s += NWARP;
    }

    // in-flight token (RoPE'd new k from scratch, new v from input)
    if (last >= s0 && last < s1 && w == ((last - s0) % NWARP)) {
        const float* kp = &g_krot[((long)b * KVHH + kvh) * DD + d0];
        const float* vp = value + ((long)b * KVHH + kvh) * DD + d0;
        float4 kA = *(const float4*)(kp);
        float4 kB = *(const float4*)(kp + 4);
        float4 vA = *(const float4*)(vp);
        float4 vB = *(const float4*)(vp + 4);
        upd_token(kA, kB, vA, vB, qh, l_own, acc, odd);
    }

    // stash per-warp partials: lane covers heads {2hi,2hi+1}, dims d0..d0+7
#pragma unroll
    for (int j = 0; j < 2; j++) {
        *(float4*)&wacc[w][2 * hi + j][d0]     = acc[j][0];
        *(float4*)&wacc[w][2 * hi + j][d0 + 4] = acc[j][1];
    }
    if (gl < 2) wl[w][2 * hi + odd] = l_own;  // lanes 0,1,16,17 -> heads 0..3
    __syncthreads();

    const long pbase = ((long)(b * KVHH + kvh) * NSPLIT + split) * GG;
    for (int i = tid; i < GG * DD; i += NTHREADS) {
        int g = i >> 7, d = i & 127;
        float t = 0.f;
#pragma unroll
        for (int ww = 0; ww < NWARP; ww++) t += wacc[ww][g][d];
        g_pacc[(pbase + g) * DD + d] = t;
    }
    if (tid < GG) {
        float L = 0.f;
#pragma unroll
        for (int ww = 0; ww < NWARP; ww++) L += wl[ww][tid];
        g_pl[pbase + tid] = L;
    }
}

// ---------------- combine (plain sums) ----------------
__global__ __launch_bounds__(DD) void pa_combine_kernel(float* __restrict__ out) {
    const int idx = blockIdx.x;             // B*KVH*G
    const int g   = idx % GG;
    const int kvh = (idx / GG) % KVHH;
    const int b   = idx / (GG * KVHH);
    const int d   = threadIdx.x;

    const long base = ((long)(b * KVHH + kvh) * NSPLIT) * GG + g;
    float L = 0.f, o = 0.f;
#pragma unroll
    for (int s = 0; s < NSPLIT; s++) {
        L += g_pl[base + (long)s * GG];
        o += g_pacc[(base + (long)s * GG) * DD + d];
    }
    out[((long)b * HH + kvh * GG + g) * DD + d] = o / L;
}

extern "C" void kernel_launch(void* const* d_in, const int* in_sizes, int n_in,
                              void* d_out, int out_size) {
    const float* query  = (const float*)d_in[0];
    const float* key    = (const float*)d_in[1];
    const float* value  = (const float*)d_in[2];
    const float* k_cache = (const float*)d_in[3];
    const float* v_cache = (const float*)d_in[4];
    const int*   block_table  = (const int*)d_in[5];
    const int*   context_lens = (const int*)d_in[6];
    float* out = (float*)d_out;

    dim3 pgrid(BB, HH + KVHH);
    rope_prep_kernel<<<pgrid, DD>>>(query, key, context_lens);

    dim3 grid(NSPLIT, KVHH, BB);
    pa_split_kernel<<<grid, NTHREADS>>>(value, k_cache, v_cache,
                                        block_table, context_lens);
    pa_combine_kernel<<<BB * KVHH * GG, DD>>>(out);
}